// round 4
// baseline (speedup 1.0000x reference)
#include <cuda_runtime.h>
#include <cuda_fp16.h>
#include <cstdint>

// GCMCGraphConv fused kernel v4 (sm_100a)
//
//   pa = sigmoid(feat @ prob_w.T); rs = sigmoid(feat @ rsw.T)
//   rf = (feat @ review_w.T) * rs
//   out[d] += (weight[src]*pa + rf) * cj[src] * ci[d]
//
// v4 vs v3 (244us, L1 87.4% busy ~213us):
//  - feat staged via warp-private double-buffered cp.async.cg (coalesced,
//    L1-bypassing loads) instead of 8-line LDG.64 gathers: the biggest L1
//    consumer (~320 cyc/32 edges) drops to ~130.
//  - XOR-swizzled A smem layout (j ^= r&7), mma k-slots remapped to
//    k = 16ks+4t+{0..3}: one conflict-free LDS.128 per row per k-step.
//  - zero __syncthreads in the main loop (warp-private stages, __syncwarp).
//  - 12 warps x 384 threads, 215KB smem, 1 block/SM, prefetch depth 1 tile.

#define OUT_DIM 64
#define THREADS 384
#define WARPS   12
#define TILE_E  384            // 12 warps x 32 edges
#define NT      9              // 8 rf n-tiles + 1 gate n-tile

#define A_STAGE_FLOATS (32 * 64)
#define A_FLOATS (WARPS * 2 * A_STAGE_FLOATS)
#define SMEM_BYTES (A_FLOATS * 4 + NT * 4 * 32 * 16)

__device__ __forceinline__ void mma16816(float c[4],
    unsigned a0, unsigned a1, unsigned a2, unsigned a3,
    unsigned b0, unsigned b1)
{
    asm volatile(
      "mma.sync.aligned.m16n8k16.row.col.f32.f16.f16.f32 "
      "{%0,%1,%2,%3}, {%4,%5,%6,%7}, {%8,%9}, {%0,%1,%2,%3};\n"
      : "+f"(c[0]), "+f"(c[1]), "+f"(c[2]), "+f"(c[3])
      : "r"(a0), "r"(a1), "r"(a2), "r"(a3), "r"(b0), "r"(b1));
}

__device__ __forceinline__ void red_add_v4(float* p, float4 v) {
    asm volatile("red.global.add.v4.f32 [%0], {%1,%2,%3,%4};"
                 :: "l"(p), "f"(v.x), "f"(v.y), "f"(v.z), "f"(v.w) : "memory");
}

__device__ __forceinline__ unsigned packh2(float a, float b) {
    __half2 h = __floats2half2_rn(a, b);
    return *(unsigned*)&h;
}
__device__ __forceinline__ float2 h2f2(unsigned u) {
    __half2 h = *(__half2*)&u;
    return __half22float2(h);
}
__device__ __forceinline__ void split2(float a, float b, unsigned& hi, unsigned& lo) {
    hi = packh2(a, b);
    float2 f = h2f2(hi);
    lo = packh2(a - f.x, b - f.y);
}

__device__ __forceinline__ void cp16(unsigned dst_s, const void* src) {
    asm volatile("cp.async.cg.shared.global [%0], [%1], 16;"
                 :: "r"(dst_s), "l"(src) : "memory");
}
__device__ __forceinline__ void cp_commit() {
    asm volatile("cp.async.commit_group;" ::: "memory");
}
__device__ __forceinline__ void cp_wait1() {
    asm volatile("cp.async.wait_group 1;" ::: "memory");
}

__global__ void __launch_bounds__(THREADS, 1)
gcmc_kernel(const float* __restrict__ weight,      // [N_SRC,64]
            const float* __restrict__ prob_w,      // [64]
            const float* __restrict__ rsw,         // [64]
            const float* __restrict__ review_w,    // [64,64]
            const float* __restrict__ feat,        // [E,64]
            const float* __restrict__ cj,          // [N_SRC]
            const float* __restrict__ ci,          // [N_DST]
            const int*   __restrict__ src_idx,     // [E]
            const int*   __restrict__ dst_idx,     // [E]
            float* __restrict__ out,               // [N_DST,64]
            int E, int n_tiles)
{
    extern __shared__ char smraw[];
    float* Abuf = (float*)smraw;                       // [WARPS][2][32*64]
    uint4 (*Btab)[4][32] = (uint4(*)[4][32])(smraw + A_FLOATS * 4);

    const int tid  = threadIdx.x;
    const int lane = tid & 31;
    const int warp = tid >> 5;
    const int g    = lane >> 2;   // 0..7
    const int t    = lane & 3;    // 0..3

    // ---- build B fragments once (fp16 hi/lo, k-slots = 16ks+4t+{0..3}) ----
    for (int i = tid; i < NT * 4 * 32; i += THREADS) {
        int l  = i & 31;
        int ks = (i >> 5) & 3;
        int nt = i >> 7;
        int gg = l >> 2, tt = l & 3;
        int k0 = 16 * ks + 4 * tt;
        float w0 = 0.f, w1 = 0.f, w2 = 0.f, w3 = 0.f;
        if (nt < 8) {
            const float* W = review_w + (nt * 8 + gg) * OUT_DIM;
            w0 = W[k0]; w1 = W[k0 + 1]; w2 = W[k0 + 2]; w3 = W[k0 + 3];
        } else if (gg == 0) {   // gate col 64 = pa dot (prob_w)
            w0 = prob_w[k0]; w1 = prob_w[k0 + 1];
            w2 = prob_w[k0 + 2]; w3 = prob_w[k0 + 3];
        } else if (gg == 1) {   // gate col 65 = rs dot (review_score_w)
            w0 = rsw[k0]; w1 = rsw[k0 + 1];
            w2 = rsw[k0 + 2]; w3 = rsw[k0 + 3];
        }
        unsigned bh0, bl0, bh1, bl1;
        split2(w0, w1, bh0, bl0);
        split2(w2, w3, bh1, bl1);
        Btab[nt][ks][l] = make_uint4(bh0, bh1, bl0, bl1);
    }
    __syncthreads();

    const int rb = warp * 32;
    float* Aw = Abuf + (warp * 2) * A_STAGE_FLOATS;
    const unsigned a_base = (unsigned)__cvta_generic_to_shared(Aw);

    // cp.async issue of one warp's 32-row feat slice into stage s
    auto issue = [&](int tile, int s) {
        if (tile < n_tiles) {
            const unsigned sb = a_base + (unsigned)s * (A_STAGE_FLOATS * 4);
            const int base_row = tile * TILE_E + rb;
            #pragma unroll
            for (int i = 0; i < 16; i++) {
                int chunk = i * 32 + lane;       // 0..511
                int r = chunk >> 4;              // 0..31
                int j = chunk & 15;              // 16B chunk within row
                int e = base_row + r;
                if (e >= E) e = E - 1;
                const float* src = feat + (size_t)e * OUT_DIM + j * 4;
                unsigned dst = sb + (unsigned)(r * 64 + ((j ^ (r & 7)) << 2)) * 4;
                cp16(dst, src);
            }
        }
        cp_commit();
    };

    const int G = gridDim.x;
    issue(blockIdx.x, 0);
    issue(blockIdx.x + G, 1);

    const unsigned FULL = 0xffffffffu;
    const int q    = lane & ~3;
    const bool odd = t & 1;
    const int coff = (t & 2) << 1;      // 0 or 4

    int s = 0;
    for (int tile = blockIdx.x; tile < n_tiles; tile += G, s ^= 1) {
        const int e0 = tile * TILE_E;

        // ---- per-thread edge metadata (4 rows: mt x {g, g+8}) ----
        int srcA[2], srcB[2], dstA[2], dstB[2];
        float ccA[2], ccB[2];
        #pragma unroll
        for (int mt = 0; mt < 2; mt++) {
            int ea = e0 + rb + 16 * mt + g;
            int eb = ea + 8;
            bool va = ea < E, vb = eb < E;
            ea = va ? ea : E - 1;
            eb = vb ? eb : E - 1;
            int sa = src_idx[ea], sb = src_idx[eb];
            int da = dst_idx[ea], db = dst_idx[eb];
            srcA[mt] = sa; srcB[mt] = sb; dstA[mt] = da; dstB[mt] = db;
            ccA[mt] = va ? cj[sa] * ci[da] : 0.f;
            ccB[mt] = vb ? cj[sb] * ci[db] : 0.f;
        }

        cp_wait1();
        __syncwarp();

        const float4* Af = (const float4*)(Aw + s * A_STAGE_FLOATS);

        // ---- GEMM: [32 rows x 72 cols] = feat @ [review_w|gates]^T ----
        float c[2][NT][4];
        #pragma unroll
        for (int mt = 0; mt < 2; mt++)
            #pragma unroll
            for (int nt = 0; nt < NT; nt++) {
                c[mt][nt][0] = 0.f; c[mt][nt][1] = 0.f;
                c[mt][nt][2] = 0.f; c[mt][nt][3] = 0.f;
            }

        #pragma unroll
        for (int ks = 0; ks < 4; ks++) {
            const int j1 = ((ks << 2) + t) ^ g;   // swizzled 16B chunk
            unsigned ah[2][4], al[2][4];
            #pragma unroll
            for (int mt = 0; mt < 2; mt++) {
                float4 v0 = Af[(16 * mt + g) * 16 + j1];       // row g
                float4 v1 = Af[(16 * mt + g + 8) * 16 + j1];   // row g+8
                split2(v0.x, v0.y, ah[mt][0], al[mt][0]);
                split2(v1.x, v1.y, ah[mt][1], al[mt][1]);
                split2(v0.z, v0.w, ah[mt][2], al[mt][2]);
                split2(v1.z, v1.w, ah[mt][3], al[mt][3]);
            }
            #pragma unroll
            for (int nt = 0; nt < NT; nt++) {
                uint4 b = Btab[nt][ks][lane];
                #pragma unroll
                for (int mt = 0; mt < 2; mt++) {
                    mma16816(c[mt][nt], ah[mt][0], ah[mt][1], ah[mt][2], ah[mt][3], b.x, b.y);
                    mma16816(c[mt][nt], ah[mt][0], ah[mt][1], ah[mt][2], ah[mt][3], b.z, b.w);
                    mma16816(c[mt][nt], al[mt][0], al[mt][1], al[mt][2], al[mt][3], b.x, b.y);
                }
            }
        }

        // stage s fully consumed by this lane; make sure all lanes are done
        // before cp.async overwrites it with tile + 2G
        __syncwarp();
        issue(tile + 2 * G, s);

        // ---- epilogue: gates, weight gather (LDG.128), scatter (red.v4) ----
        #pragma unroll
        for (int mt = 0; mt < 2; mt++) {
            float paA_ = __shfl_sync(FULL, c[mt][8][0], q);   // row g,   col 64
            float rsA_ = __shfl_sync(FULL, c[mt][8][1], q);   // row g,   col 65
            float paB_ = __shfl_sync(FULL, c[mt][8][2], q);   // row g+8, col 64
            float rsB_ = __shfl_sync(FULL, c[mt][8][3], q);   // row g+8, col 65
            float pa = odd ? paB_ : paA_;
            float rs = odd ? rsB_ : rsA_;
            pa = 1.f / (1.f + __expf(-pa));
            rs = 1.f / (1.f + __expf(-rs));
            float cc = odd ? ccB[mt] : ccA[mt];
            const float* wrow = weight + (size_t)(odd ? srcB[mt] : srcA[mt]) * OUT_DIM;
            float*       orow = out    + (size_t)(odd ? dstB[mt] : dstA[mt]) * OUT_DIM;
            #pragma unroll
            for (int nt = 0; nt < 8; nt++) {
                float x0 = __shfl_xor_sync(FULL, c[mt][nt][0], 1);
                float x1 = __shfl_xor_sync(FULL, c[mt][nt][1], 1);
                float x2 = __shfl_xor_sync(FULL, c[mt][nt][2], 1);
                float x3 = __shfl_xor_sync(FULL, c[mt][nt][3], 1);
                float r0, r1, r2, r3;
                if (!odd) { r0 = c[mt][nt][0]; r1 = c[mt][nt][1]; r2 = x0; r3 = x1; }
                else      { r0 = x2; r1 = x3; r2 = c[mt][nt][2]; r3 = c[mt][nt][3]; }
                const int col = nt * 8 + coff;
                float4 wv = *(const float4*)(wrow + col);
                float4 v;
                v.x = fmaf(wv.x, pa, r0 * rs) * cc;
                v.y = fmaf(wv.y, pa, r1 * rs) * cc;
                v.z = fmaf(wv.z, pa, r2 * rs) * cc;
                v.w = fmaf(wv.w, pa, r3 * rs) * cc;
                red_add_v4(orow + col, v);
            }
        }
    }
}

extern "C" void kernel_launch(void* const* d_in, const int* in_sizes, int n_in,
                              void* d_out, int out_size) {
    const float* weight   = (const float*)d_in[0];
    const float* prob_w   = (const float*)d_in[1];
    const float* rsw      = (const float*)d_in[2];
    const float* review_w = (const float*)d_in[3];
    const float* feat     = (const float*)d_in[4];
    const float* cj       = (const float*)d_in[5];
    const float* ci       = (const float*)d_in[6];
    const int*   src_idx  = (const int*)d_in[7];
    const int*   dst_idx  = (const int*)d_in[8];
    float* out = (float*)d_out;

    const int E = in_sizes[4] / OUT_DIM;
    const int n_tiles = (E + TILE_E - 1) / TILE_E;

    cudaMemsetAsync(d_out, 0, (size_t)out_size * sizeof(float), 0);

    static int smem_set = 0;
    if (!smem_set) {
        cudaFuncSetAttribute(gcmc_kernel,
                             cudaFuncAttributeMaxDynamicSharedMemorySize,
                             SMEM_BYTES);
        smem_set = 1;
    }

    int grid = n_tiles < 148 ? n_tiles : 148;   // persistent, 1 block/SM
    gcmc_kernel<<<grid, THREADS, SMEM_BYTES, 0>>>(
        weight, prob_w, rsw, review_w, feat, cj, ci, src_idx, dst_idx,
        out, E, n_tiles);
}

// round 5
// speedup vs baseline: 1.2804x; 1.2804x over previous
#include <cuda_runtime.h>
#include <cuda_fp16.h>
#include <cstdint>

// GCMCGraphConv fused kernel v5 (sm_100a)
//
//   pa = sigmoid(feat @ prob_w.T); rs = sigmoid(feat @ rsw.T)
//   rf = (feat @ review_w.T) * rs
//   out[d] += (weight[src]*pa + rf) * cj[src] * ci[d]
//
// v5 vs v3 (244us) / v4 (252us, occupancy regression):
//  - A: k-slots = 16ks+4t+{0..3} -> one LDG.128 per row per k-step straight
//    from GMEM (128 wf vs 256). No staging (v4 lesson: keep 16 warps/SM).
//  - epilogue: c written to a warp-private smem tile (rotation-swizzled,
//    conflict-free STS.64) and read back row-major: weight gather and
//    red.v4 scatter touch only 2 rows per warp instruction (64 wf vs 256
//    each). All shuffles gone; sigmoid*cjci folded at write time.
//  - 2 blocks x 256 threads, <=128 regs, ~89KB smem/block.

#define OUT_DIM 64
#define THREADS 256
#define WARPS   8
#define TILE_E  256
#define NT      9

// per-warp epilogue buffers
#define CBUF_FLOATS (32 * 64)                 // 8192 B
#define WBUF_FLOATS (CBUF_FLOATS + 32 * 4 + 32)   // + rbuf(f4) + ccb
#define SMEM_FLOATS (WARPS * WBUF_FLOATS + NT * 4 * 32 * 4)
#define SMEM_BYTES  (SMEM_FLOATS * 4)

__device__ __forceinline__ void mma16816(float c[4],
    unsigned a0, unsigned a1, unsigned a2, unsigned a3,
    unsigned b0, unsigned b1)
{
    asm volatile(
      "mma.sync.aligned.m16n8k16.row.col.f32.f16.f16.f32 "
      "{%0,%1,%2,%3}, {%4,%5,%6,%7}, {%8,%9}, {%0,%1,%2,%3};\n"
      : "+f"(c[0]), "+f"(c[1]), "+f"(c[2]), "+f"(c[3])
      : "r"(a0), "r"(a1), "r"(a2), "r"(a3), "r"(b0), "r"(b1));
}

__device__ __forceinline__ void red_add_v4(float* p, float4 v) {
    asm volatile("red.global.add.v4.f32 [%0], {%1,%2,%3,%4};"
                 :: "l"(p), "f"(v.x), "f"(v.y), "f"(v.z), "f"(v.w) : "memory");
}

__device__ __forceinline__ unsigned packh2(float a, float b) {
    __half2 h = __floats2half2_rn(a, b);
    return *(unsigned*)&h;
}
__device__ __forceinline__ float2 h2f2(unsigned u) {
    __half2 h = *(__half2*)&u;
    return __half22float2(h);
}
__device__ __forceinline__ void split2(float a, float b, unsigned& hi, unsigned& lo) {
    hi = packh2(a, b);
    float2 f = h2f2(hi);
    lo = packh2(a - f.x, b - f.y);
}
__device__ __forceinline__ float sigmoidf_(float x) {
    return 1.f / (1.f + __expf(-x));
}

__global__ void __launch_bounds__(THREADS, 2)
gcmc_kernel(const float* __restrict__ weight,      // [N_SRC,64]
            const float* __restrict__ prob_w,      // [64]
            const float* __restrict__ rsw,         // [64]
            const float* __restrict__ review_w,    // [64,64]
            const float* __restrict__ feat,        // [E,64]
            const float* __restrict__ cj,          // [N_SRC]
            const float* __restrict__ ci,          // [N_DST]
            const int*   __restrict__ src_idx,     // [E]
            const int*   __restrict__ dst_idx,     // [E]
            float* __restrict__ out,               // [N_DST,64]
            int E, int n_tiles)
{
    extern __shared__ float smf[];

    const int tid  = threadIdx.x;
    const int lane = tid & 31;
    const int warp = tid >> 5;
    const int g    = lane >> 2;   // 0..7
    const int t    = lane & 3;    // 0..3

    float*  cbuf = smf + warp * WBUF_FLOATS;            // [32][64] rotated
    float4* rbuf = (float4*)(cbuf + CBUF_FLOATS);       // [32] {pa*cc, rs*cc, src, dst}
    float*  ccb  = cbuf + CBUF_FLOATS + 128;            // [32] cj*ci
    uint4 (*Btab)[4][32] = (uint4(*)[4][32])(smf + WARPS * WBUF_FLOATS);

    // ---- build B fragments once (fp16 hi/lo; slots k = 16ks+4t+{0..3}) ----
    for (int i = tid; i < NT * 4 * 32; i += THREADS) {
        int l  = i & 31;
        int ks = (i >> 5) & 3;
        int nt = i >> 7;
        int gg = l >> 2, tt = l & 3;
        int k0 = 16 * ks + 4 * tt;
        float w0 = 0.f, w1 = 0.f, w2 = 0.f, w3 = 0.f;
        if (nt < 8) {
            const float* W = review_w + (nt * 8 + gg) * OUT_DIM;
            w0 = W[k0]; w1 = W[k0 + 1]; w2 = W[k0 + 2]; w3 = W[k0 + 3];
        } else if (gg == 0) {   // gate col 64 = pa (prob_w)
            w0 = prob_w[k0]; w1 = prob_w[k0 + 1];
            w2 = prob_w[k0 + 2]; w3 = prob_w[k0 + 3];
        } else if (gg == 1) {   // gate col 65 = rs (review_score_w)
            w0 = rsw[k0]; w1 = rsw[k0 + 1];
            w2 = rsw[k0 + 2]; w3 = rsw[k0 + 3];
        }
        unsigned bh0, bl0, bh1, bl1;
        split2(w0, w1, bh0, bl0);
        split2(w2, w3, bh1, bl1);
        Btab[nt][ks][l] = make_uint4(bh0, bh1, bl0, bl1);
    }
    __syncthreads();

    const int rb = warp * 32;
    const int half = lane >> 4;      // epilogue: 0/1 -> which of 2 rows
    const int j    = lane & 15;      // epilogue: 16B chunk within row

    for (int tile = blockIdx.x; tile < n_tiles; tile += gridDim.x) {
        const int e0 = tile * TILE_E + rb;

        // ---- meta: 1 edge per lane -> ccb, rbuf.zw (src,dst) ----
        {
            int e = e0 + lane;
            bool v = e < E;
            int ec = v ? e : E - 1;
            int s_ = src_idx[ec], d_ = dst_idx[ec];
            float cc = v ? cj[s_] * ci[d_] : 0.f;
            ccb[lane] = cc;
            ((float2*)&rbuf[lane])[1] =
                make_float2(__int_as_float(s_), __int_as_float(d_));
        }
        __syncwarp();

        // ---- GEMM: [32 rows x 72 cols] straight from GMEM A ----
        float c[2][NT][4];
        #pragma unroll
        for (int mt = 0; mt < 2; mt++)
            #pragma unroll
            for (int nt = 0; nt < NT; nt++) {
                c[mt][nt][0] = 0.f; c[mt][nt][1] = 0.f;
                c[mt][nt][2] = 0.f; c[mt][nt][3] = 0.f;
            }

        const float* fA[2];
        const float* fB[2];
        #pragma unroll
        for (int mt = 0; mt < 2; mt++) {
            int ea = e0 + 16 * mt + g;
            int eb = ea + 8;
            fA[mt] = feat + (size_t)(ea < E ? ea : E - 1) * OUT_DIM;
            fB[mt] = feat + (size_t)(eb < E ? eb : E - 1) * OUT_DIM;
        }

        #pragma unroll
        for (int ks = 0; ks < 4; ks++) {
            const int ko = 16 * ks + 4 * t;
            unsigned ah[2][4], al[2][4];
            #pragma unroll
            for (int mt = 0; mt < 2; mt++) {
                float4 v0 = *(const float4*)(fA[mt] + ko);   // row g
                float4 v1 = *(const float4*)(fB[mt] + ko);   // row g+8
                split2(v0.x, v0.y, ah[mt][0], al[mt][0]);
                split2(v1.x, v1.y, ah[mt][1], al[mt][1]);
                split2(v0.z, v0.w, ah[mt][2], al[mt][2]);
                split2(v1.z, v1.w, ah[mt][3], al[mt][3]);
            }
            #pragma unroll
            for (int nt = 0; nt < NT; nt++) {
                uint4 b = Btab[nt][ks][lane];
                #pragma unroll
                for (int mt = 0; mt < 2; mt++) {
                    mma16816(c[mt][nt], ah[mt][0], ah[mt][1], ah[mt][2], ah[mt][3], b.x, b.y);
                    mma16816(c[mt][nt], ah[mt][0], ah[mt][1], ah[mt][2], ah[mt][3], b.z, b.w);
                    mma16816(c[mt][nt], al[mt][0], al[mt][1], al[mt][2], al[mt][3], b.x, b.y);
                }
            }
        }

        // ---- write c to warp-private smem (rotation ch2=(4nt+t+4(r&3))&31,
        //      conflict-free STS.64 on both row groups) ----
        #pragma unroll
        for (int mt = 0; mt < 2; mt++) {
            const int r0 = 16 * mt + g;
            const int rot = 4 * (r0 & 3);
            #pragma unroll
            for (int nt = 0; nt < 8; nt++) {
                const int ch2 = (4 * nt + t + rot) & 31;
                *(float2*)(cbuf + r0 * 64 + 2 * ch2) =
                    make_float2(c[mt][nt][0], c[mt][nt][1]);
                *(float2*)(cbuf + (r0 + 8) * 64 + 2 * ch2) =
                    make_float2(c[mt][nt][2], c[mt][nt][3]);
            }
        }
        // gates: t==0 lanes hold cols 64(pa),65(rs); fold sigmoid * cjci
        if (t == 0) {
            #pragma unroll
            for (int mt = 0; mt < 2; mt++) {
                const int r0 = 16 * mt + g, r1 = r0 + 8;
                float cc0 = ccb[r0], cc1 = ccb[r1];
                ((float2*)&rbuf[r0])[0] = make_float2(
                    sigmoidf_(c[mt][8][0]) * cc0, sigmoidf_(c[mt][8][1]) * cc0);
                ((float2*)&rbuf[r1])[0] = make_float2(
                    sigmoidf_(c[mt][8][2]) * cc1, sigmoidf_(c[mt][8][3]) * cc1);
            }
        }
        __syncwarp();

        // ---- row-major epilogue: 2 edge rows per warp instruction ----
        #pragma unroll
        for (int i = 0; i < 16; i++) {
            const int r = 2 * i + half;
            float4 cv = *(const float4*)(cbuf + r * 64 + j * 4);
            const int cn2 = (2 * j - 4 * (r & 3)) & 31;   // even
            const int col = 2 * cn2;                       // 16B aligned
            float4 q = rbuf[r];                            // {paC, rsC, src, dst}
            int sx = __float_as_int(q.z);
            int dx = __float_as_int(q.w);
            float4 wv = *(const float4*)(weight + (size_t)sx * OUT_DIM + col);
            float4 o;
            o.x = fmaf(wv.x, q.x, cv.x * q.y);
            o.y = fmaf(wv.y, q.x, cv.y * q.y);
            o.z = fmaf(wv.z, q.x, cv.z * q.y);
            o.w = fmaf(wv.w, q.x, cv.w * q.y);
            red_add_v4(out + (size_t)dx * OUT_DIM + col, o);
        }
        __syncwarp();   // buffers reused next tile (warp-private)
    }
}

extern "C" void kernel_launch(void* const* d_in, const int* in_sizes, int n_in,
                              void* d_out, int out_size) {
    const float* weight   = (const float*)d_in[0];
    const float* prob_w   = (const float*)d_in[1];
    const float* rsw      = (const float*)d_in[2];
    const float* review_w = (const float*)d_in[3];
    const float* feat     = (const float*)d_in[4];
    const float* cj       = (const float*)d_in[5];
    const float* ci       = (const float*)d_in[6];
    const int*   src_idx  = (const int*)d_in[7];
    const int*   dst_idx  = (const int*)d_in[8];
    float* out = (float*)d_out;

    const int E = in_sizes[4] / OUT_DIM;
    const int n_tiles = (E + TILE_E - 1) / TILE_E;

    cudaMemsetAsync(d_out, 0, (size_t)out_size * sizeof(float), 0);

    static int smem_set = 0;
    if (!smem_set) {
        cudaFuncSetAttribute(gcmc_kernel,
                             cudaFuncAttributeMaxDynamicSharedMemorySize,
                             SMEM_BYTES);
        smem_set = 1;
    }

    int grid = n_tiles < 296 ? n_tiles : 296;   // 2 persistent blocks / SM
    gcmc_kernel<<<grid, THREADS, SMEM_BYTES, 0>>>(
        weight, prob_w, rsw, review_w, feat, cj, ci, src_idx, dst_idx,
        out, E, n_tiles);
}